// round 11
// baseline (speedup 1.0000x reference)
#include <cuda_runtime.h>
#include <cstdint>

// ---------------- problem constants ----------------
#define BATCH   32
#define CH      512
#define HW      3136
#define NCL     27
#define TOTPX   (BATCH * HW)
#define PROBS_ELEMS (BATCH * NCL * HW)

#define MTILE   128                 // pixels per tile
#define TILES_PER_B 25              // ceil(3136/128), last tile 64 valid
#define NTILES  (BATCH * TILES_PER_B)   // 800
#define TPB     128
#define OCC     6
#define CCH     8                   // channels per chunk (K step)
#define NCHUNKS (CH / CCH)          // 64
#define NPADN   32                  // clusters padded to 32 (rows 27-31 zero)

// ---------------- smem: per-WARP private 5-stage ring, epilogue unioned ----------------
#define SSTR    40                              // floats per k-row (40%32==8 -> conflict-free)
#define STG_W   (CCH * SSTR * 4)                // 1280 B per warp-stage
#define STAGES  5
#define WARP_BLOB (STAGES * STG_W)              // 6400 B per warp (>= epilogue 4352)
#define SMEM_BYTES (4 * WARP_BLOB)              // 25600

// ---------------- device scratch ----------------
__device__ float  g_nhi[NPADN * CH];   // rna(tf32) normalized clusters, pad rows zero
__device__ double g_accum;
__device__ int    g_done;              // CTA completion ticket

// ---------------- helpers ----------------
__device__ __forceinline__ float tf32_rna(float x) {
    uint32_t u;
    asm("cvt.rna.tf32.f32 %0, %1;" : "=r"(u) : "f"(x));
    return __uint_as_float(u);
}
__device__ __forceinline__ void mma_tf32(float* d, const uint32_t* a, const uint32_t* b) {
    asm volatile(
        "mma.sync.aligned.m16n8k8.row.col.f32.tf32.tf32.f32 "
        "{%0,%1,%2,%3}, {%4,%5,%6,%7}, {%8,%9}, {%0,%1,%2,%3};"
        : "+f"(d[0]), "+f"(d[1]), "+f"(d[2]), "+f"(d[3])
        : "r"(a[0]), "r"(a[1]), "r"(a[2]), "r"(a[3]), "r"(b[0]), "r"(b[1]));
}
__device__ __forceinline__ void cp16(uint32_t dst, const void* src, int nbytes) {
    asm volatile("cp.async.cg.shared.global [%0], [%1], 16, %2;"
                 :: "r"(dst), "l"(src), "r"(nbytes) : "memory");
}
#define CP_COMMIT()  asm volatile("cp.async.commit_group;" ::: "memory")
#define CP_WAIT4()   asm volatile("cp.async.wait_group 4;" ::: "memory")
#define CP_WAIT0()   asm volatile("cp.async.wait_group 0;" ::: "memory")

// ---------------- Kernel A: normalize clusters, rna-rounded ----------------
__global__ void normalize_clusters(const float* __restrict__ clusters) {
    __shared__ float swarp[8];
    const int n = blockIdx.x;
    const int tid = threadIdx.x, lane = tid & 31, w = tid >> 5;
    if (n >= NCL) {       // pad block: zero rows 27-31, reset accum + ticket
        for (int i = tid; i < (NPADN - NCL) * CH; i += 256) g_nhi[NCL * CH + i] = 0.0f;
        if (tid == 0) { g_accum = 0.0; g_done = 0; }
        return;
    }
    const float* row = clusters + (size_t)n * CH;
    float ss = 0.0f;
    for (int c = tid; c < CH; c += 256) { float v = row[c]; ss += v * v; }
    #pragma unroll
    for (int o = 16; o > 0; o >>= 1) ss += __shfl_xor_sync(0xffffffffu, ss, o);
    if (lane == 0) swarp[w] = ss;
    __syncthreads();
    if (tid == 0) {
        float t = 0.0f;
        #pragma unroll
        for (int i = 0; i < 8; ++i) t += swarp[i];
        swarp[0] = t;
    }
    __syncthreads();
    const float inv = 1.0f / fmaxf(sqrtf(swarp[0]), 1e-12f);
    for (int c = tid; c < CH; c += 256)
        g_nhi[n * CH + c] = tf32_rna(row[c] * inv);
}

// ---------------- Kernel B: warp-private tf32 HMMA pipeline ----------------
__global__ void __launch_bounds__(TPB, OCC)
cluster_main(const float* __restrict__ x, float* __restrict__ probs,
             float* __restrict__ loss) {
    __shared__ __align__(16) char sm[SMEM_BYTES];
    __shared__ float sred[4];

    const int tid  = threadIdx.x;
    const int lane = tid & 31;
    const int warp = tid >> 5;
    const uint32_t smb   = (uint32_t)__cvta_generic_to_shared(sm);
    const uint32_t wring = smb + (uint32_t)warp * WARP_BLOB;

    const int g    = blockIdx.x;
    const int b    = g / TILES_PER_B;
    const int tile = g % TILES_PER_B;
    const int pix  = tile * MTILE + tid;
    const bool valid  = (pix < HW);
    const bool wvalid = (tile * MTILE + warp * 32 + 32 <= HW);  // whole warp in range
    const float* xtile = x + (size_t)b * CH * HW + tile * MTILE;

    // x cp.async: lane -> (channel xch, pixel-group xpg); 2x16B per chunk
    const int xch = lane >> 2;
    const int xpg = lane & 3;
    const float* xsrc = xtile + (size_t)xch * HW + warp * 32 + xpg * 4;
    const int xbytes = wvalid ? 16 : 0;
    const uint32_t dst0 = (uint32_t)xch * (SSTR * 4) + xpg * 16;
    const uint32_t dst1 = dst0 + 64;

    // B fragment gmem base (row = lane>>2 within 8-row group, col = lane&3)
    const float* const bbase = g_nhi + (size_t)(lane >> 2) * CH + (lane & 3);

    // A fragment byte offsets within a stage
    int fo[2];
    #pragma unroll
    for (int mt = 0; mt < 2; ++mt)
        fo[mt] = ((lane & 3) * SSTR + mt * 16 + (lane >> 2)) * 4;

    uint32_t wbase = wring;
    const float* xs_src = xsrc;
    auto issue = [&]() {
        cp16(wbase + dst0, wvalid ? (const void*)xs_src : (const void*)xtile, xbytes);
        cp16(wbase + dst1, wvalid ? (const void*)(xs_src + 16) : (const void*)xtile, xbytes);
        xs_src += (size_t)CCH * HW;
        wbase += STG_W;
        if (wbase == wring + WARP_BLOB) wbase = wring;
    };

    float d[2][4][4];
    #pragma unroll
    for (int mt = 0; mt < 2; ++mt)
        #pragma unroll
        for (int nt = 0; nt < 4; ++nt)
            #pragma unroll
            for (int i = 0; i < 4; ++i) d[mt][nt][i] = 0.0f;
    float ssr[2][2] = {{0.f, 0.f}, {0.f, 0.f}};

    // prime 4 stages
    issue(); CP_COMMIT();
    issue(); CP_COMMIT();
    issue(); CP_COMMIT();
    issue(); CP_COMMIT();

    // B fragments for chunk 0
    uint32_t bcur[4][2];
    #pragma unroll
    for (int nt = 0; nt < 4; ++nt) {
        bcur[nt][0] = __float_as_uint(__ldg(bbase + (size_t)nt * 8 * CH));
        bcur[nt][1] = __float_as_uint(__ldg(bbase + (size_t)nt * 8 * CH + 4));
    }

    uint32_t rbase = wring;
    #pragma unroll 2
    for (int kc = 0; kc < NCHUNKS; ++kc) {
        if (kc + 4 < NCHUNKS) issue();
        CP_COMMIT();
        CP_WAIT4();
        __syncwarp();

        // prefetch B for kc+1 (L1-hot)
        uint32_t bnext[4][2];
        if (kc + 1 < NCHUNKS) {
            const float* bp = bbase + (kc + 1) * CCH;
            #pragma unroll
            for (int nt = 0; nt < 4; ++nt) {
                bnext[nt][0] = __float_as_uint(__ldg(bp + (size_t)nt * 8 * CH));
                bnext[nt][1] = __float_as_uint(__ldg(bp + (size_t)nt * 8 * CH + 4));
            }
        }

        const char* sbase = (const char*)sm + (rbase - smb);
        uint32_t ah[2][4];
        #pragma unroll
        for (int mt = 0; mt < 2; ++mt) {
            const float* xp = (const float*)(sbase + fo[mt]);
            const float r0 = xp[0];
            const float r1 = xp[8];
            const float r2 = xp[4 * SSTR];
            const float r3 = xp[4 * SSTR + 8];
            ssr[mt][0] = fmaf(r0, r0, fmaf(r2, r2, ssr[mt][0]));
            ssr[mt][1] = fmaf(r1, r1, fmaf(r3, r3, ssr[mt][1]));
            ah[mt][0] = __float_as_uint(tf32_rna(r0));
            ah[mt][1] = __float_as_uint(tf32_rna(r1));
            ah[mt][2] = __float_as_uint(tf32_rna(r2));
            ah[mt][3] = __float_as_uint(tf32_rna(r3));
        }
        #pragma unroll
        for (int mt = 0; mt < 2; ++mt)
            #pragma unroll
            for (int nt = 0; nt < 4; ++nt)
                mma_tf32(d[mt][nt], ah[mt], bcur[nt]);

        #pragma unroll
        for (int nt = 0; nt < 4; ++nt) {
            bcur[nt][0] = bnext[nt][0];
            bcur[nt][1] = bnext[nt][1];
        }
        rbase += STG_W;
        if (rbase == wring + WARP_BLOB) rbase = wring;
    }

    // ---- epilogue (warp-private, reuses own ring region) ----
    CP_WAIT0();
    __syncwarp();
    float* ssim_w = (float*)(sm + (size_t)warp * WARP_BLOB);   // [32 px][33]
    float* sss_w  = ssim_w + 32 * 33;                          // [32]
    #pragma unroll
    for (int mt = 0; mt < 2; ++mt) {
        const int r0 = mt * 16 + (lane >> 2);
        #pragma unroll
        for (int nt = 0; nt < 4; ++nt) {
            const int n0 = nt * 8 + (lane & 3) * 2;
            ssim_w[r0 * 33 + n0]           = d[mt][nt][0];
            ssim_w[r0 * 33 + n0 + 1]       = d[mt][nt][1];
            ssim_w[(r0 + 8) * 33 + n0]     = d[mt][nt][2];
            ssim_w[(r0 + 8) * 33 + n0 + 1] = d[mt][nt][3];
        }
    }
    #pragma unroll
    for (int mt = 0; mt < 2; ++mt)
        #pragma unroll
        for (int j = 0; j < 2; ++j) {
            float vv = ssr[mt][j];
            vv += __shfl_xor_sync(0xffffffffu, vv, 1);
            vv += __shfl_xor_sync(0xffffffffu, vv, 2);
            if ((lane & 3) == 0)
                sss_w[mt * 16 + j * 8 + (lane >> 2)] = vv;
        }
    __syncwarp();

    const float inv = 1.0f / fmaxf(sqrtf(sss_w[lane]), 1e-12f);
    float sims[NCL], m = -1e30f;
    #pragma unroll
    for (int n = 0; n < NCL; ++n) {
        sims[n] = ssim_w[lane * 33 + n] * inv;
        m = fmaxf(m, sims[n]);
    }
    float se = 0.0f, ses = 0.0f;
    #pragma unroll
    for (int n = 0; n < NCL; ++n) {
        const float e = __expf(2.0f * (sims[n] - m));
        se += e; ses += e * sims[n];
        sims[n] = e;
    }
    const float r = 1.0f / se;

    if (probs != nullptr && valid) {
        float* op = probs + (size_t)b * NCL * HW + pix;
        #pragma unroll
        for (int n = 0; n < NCL; ++n) op[(size_t)n * HW] = sims[n] * r;
    }

    // ---- loss reduction (only block-wide syncs in the kernel) ----
    float c = valid ? (ses * r) : 0.0f;
    #pragma unroll
    for (int o = 16; o > 0; o >>= 1) c += __shfl_xor_sync(0xffffffffu, c, o);
    if (lane == 0) sred[warp] = c;
    __syncthreads();
    if (tid == 0)
        atomicAdd(&g_accum, (double)(sred[0] + sred[1] + sred[2] + sred[3]));

    // ---- fused finalize: last CTA writes the loss ----
    if (tid == 0 && loss != nullptr) {
        __threadfence();
        const int t = atomicAdd(&g_done, 1);
        if (t == NTILES - 1)
            *loss = (float)(-g_accum / (double)TOTPX);
    }
}

extern "C" void kernel_launch(void* const* d_in, const int* in_sizes, int n_in,
                              void* d_out, int out_size) {
    const float* x        = (const float*)d_in[0];
    const float* clusters = (const float*)d_in[1];
    float* out = (float*)d_out;

    float* probs_ptr = nullptr;
    float* loss_ptr  = nullptr;
    if (out_size >= PROBS_ELEMS) {
        probs_ptr = out + (out_size - PROBS_ELEMS);
        if (out_size > PROBS_ELEMS) loss_ptr = out;
    } else {
        loss_ptr = out;
    }

    normalize_clusters<<<NCL + 1, 256>>>(clusters);
    cluster_main<<<NTILES, TPB>>>(x, probs_ptr, loss_ptr);
}

// round 12
// speedup vs baseline: 1.3896x; 1.3896x over previous
#include <cuda_runtime.h>
#include <cstdint>

// ---------------- problem constants ----------------
#define BATCH   32
#define CH      512
#define HW      3136
#define NCL     27
#define TOTPX   (BATCH * HW)
#define PROBS_ELEMS (BATCH * NCL * HW)

#define MTILE   128                 // pixels per tile
#define TILES_PER_B 25              // ceil(3136/128), last tile 64 valid
#define NTILES  (BATCH * TILES_PER_B)   // 800
#define TPB     128
#define OCC     5
#define CCH     8                   // channels per chunk (K step)
#define NCHUNKS (CH / CCH)          // 64
#define NPADN   32                  // clusters padded to 32 (rows 27-31 zero)

// ---------------- smem: 7-stage cp.async ring, distance-6 prefetch ----------------
#define XS_STRIDE  136                              // floats, conflict-free frags
#define XSTG_BYTES (CCH * XS_STRIDE * 4)            // 4352 (x raw)
#define SB_STRIDE  12
#define BSTG_BYTES (NPADN * SB_STRIDE * 4)          // 1536 (B tf32-rna)
#define STG_BYTES  (XSTG_BYTES + BSTG_BYTES)        // 5888
#define STAGES     7
#define DIST       6                                // prefetch distance (chunks)
#define RING_BYTES (STAGES * STG_BYTES)             // 41216
#define SSIM_STRIDE 132
#define SSS_OFF    (NPADN * SSIM_STRIDE * 4)        // 16896 (fits in ring)
#define SMEM_BYTES RING_BYTES                       // 41216 static (< 48K)

// ---------------- device scratch ----------------
__device__ float  g_nhi[NPADN * CH];   // rna(tf32) normalized clusters, pad rows zero
__device__ double g_accum;
__device__ int    g_done;              // CTA completion ticket

// ---------------- helpers ----------------
__device__ __forceinline__ float tf32_rna(float x) {
    uint32_t u;
    asm("cvt.rna.tf32.f32 %0, %1;" : "=r"(u) : "f"(x));
    return __uint_as_float(u);
}
__device__ __forceinline__ void mma_tf32(float* d, const uint32_t* a, const uint32_t* b) {
    asm volatile(
        "mma.sync.aligned.m16n8k8.row.col.f32.tf32.tf32.f32 "
        "{%0,%1,%2,%3}, {%4,%5,%6,%7}, {%8,%9}, {%0,%1,%2,%3};"
        : "+f"(d[0]), "+f"(d[1]), "+f"(d[2]), "+f"(d[3])
        : "r"(a[0]), "r"(a[1]), "r"(a[2]), "r"(a[3]), "r"(b[0]), "r"(b[1]));
}
__device__ __forceinline__ void cp16(uint32_t dst, const void* src, int nbytes) {
    asm volatile("cp.async.cg.shared.global [%0], [%1], 16, %2;"
                 :: "r"(dst), "l"(src), "r"(nbytes) : "memory");
}
#define CP_COMMIT()  asm volatile("cp.async.commit_group;" ::: "memory")
#define CP_WAIT5()   asm volatile("cp.async.wait_group 5;" ::: "memory")
#define CP_WAIT0()   asm volatile("cp.async.wait_group 0;" ::: "memory")

// ---------------- Kernel A: normalize clusters, rna-rounded ----------------
__global__ void normalize_clusters(const float* __restrict__ clusters) {
    __shared__ float swarp[8];
    const int n = blockIdx.x;
    const int tid = threadIdx.x, lane = tid & 31, w = tid >> 5;
    if (n >= NCL) {       // pad block: zero rows 27-31, reset accum + ticket
        for (int i = tid; i < (NPADN - NCL) * CH; i += 256) g_nhi[NCL * CH + i] = 0.0f;
        if (tid == 0) { g_accum = 0.0; g_done = 0; }
        return;
    }
    const float* row = clusters + (size_t)n * CH;
    float ss = 0.0f;
    for (int c = tid; c < CH; c += 256) { float v = row[c]; ss += v * v; }
    #pragma unroll
    for (int o = 16; o > 0; o >>= 1) ss += __shfl_xor_sync(0xffffffffu, ss, o);
    if (lane == 0) swarp[w] = ss;
    __syncthreads();
    if (tid == 0) {
        float t = 0.0f;
        #pragma unroll
        for (int i = 0; i < 8; ++i) t += swarp[i];
        swarp[0] = t;
    }
    __syncthreads();
    const float inv = 1.0f / fmaxf(sqrtf(swarp[0]), 1e-12f);
    for (int c = tid; c < CH; c += 256)
        g_nhi[n * CH + c] = tf32_rna(row[c] * inv);
}

// ---------------- Kernel B: tf32 HMMA, 7-stage distance-6 cp.async pipeline ----------------
__global__ void __launch_bounds__(TPB, OCC)
cluster_main(const float* __restrict__ x, float* __restrict__ probs,
             float* __restrict__ loss) {
    __shared__ __align__(16) char sm[SMEM_BYTES];
    __shared__ float sred[4];

    const int tid  = threadIdx.x;
    const int lane = tid & 31;
    const int warp = tid >> 5;
    const uint32_t smb = (uint32_t)__cvta_generic_to_shared(sm);
    const int wpx = warp * 32;

    const int g    = blockIdx.x;
    const int b    = g / TILES_PER_B;
    const int tile = g % TILES_PER_B;
    const int pix  = tile * MTILE + tid;
    const bool valid = (pix < HW);
    const float* xtile = x + (size_t)b * CH * HW + tile * MTILE;

    const bool seg_ok = (tile * MTILE + lane * 4 + 4 <= HW);
    const int xbytes = seg_ok ? 16 : 0;

    // constant per-thread byte offsets
    const uint32_t xoff0 = (uint32_t)warp * (XS_STRIDE * 4) + lane * 16;
    const uint32_t xoff1 = (uint32_t)(warp + 4) * (XS_STRIDE * 4) + lane * 16;
    const int brow  = (tid & 63) >> 1;
    const int bhalf = tid & 1;
    const uint32_t boff = XSTG_BYTES + brow * (SB_STRIDE * 4) + bhalf * 16;
    const bool do_b = (tid < 64);

    // fragment byte offsets within a stage
    int fo[2], bo[4];
    #pragma unroll
    for (int mt = 0; mt < 2; ++mt)
        fo[mt] = ((lane & 3) * XS_STRIDE + wpx + mt * 16 + (lane >> 2)) * 4;
    #pragma unroll
    for (int nt = 0; nt < 4; ++nt)
        bo[nt] = XSTG_BYTES + ((nt * 8 + (lane >> 2)) * SB_STRIDE + (lane & 3)) * 4;

    // incremental producer state
    const float* xsrc = xtile + (size_t)warp * HW + lane * 4;
    const float* bsrc = g_nhi + (size_t)brow * CH + bhalf * 4;
    uint32_t wbase = smb;
    auto issue = [&]() {
        cp16(wbase + xoff0, seg_ok ? (const void*)xsrc : (const void*)xtile, xbytes);
        cp16(wbase + xoff1, seg_ok ? (const void*)(xsrc + (size_t)4 * HW)
                                   : (const void*)xtile, xbytes);
        if (do_b) cp16(wbase + boff, bsrc, 16);
        xsrc += (size_t)CCH * HW;
        bsrc += CCH;
        wbase += STG_BYTES;
        if (wbase == smb + RING_BYTES) wbase = smb;
    };

    float d[2][4][4];
    #pragma unroll
    for (int mt = 0; mt < 2; ++mt)
        #pragma unroll
        for (int nt = 0; nt < 4; ++nt)
            #pragma unroll
            for (int i = 0; i < 4; ++i) d[mt][nt][i] = 0.0f;
    float ssr[2][2] = {{0.f, 0.f}, {0.f, 0.f}};

    // prime DIST=6 stages
    #pragma unroll
    for (int p = 0; p < DIST; ++p) { issue(); CP_COMMIT(); }

    uint32_t rbase = smb;
    for (int kc = 0; kc < NCHUNKS; ++kc) {
        CP_WAIT5();          // own group for chunk kc complete (6 outstanding -> 5)
        __syncthreads();     // all warps' chunk-kc data visible; all past chunk kc-1
        if (kc + DIST < NCHUNKS) issue();   // post-barrier: no reader older than kc
        CP_COMMIT();         // unconditional: keeps group count invariant in tail

        const char* sbase = (const char*)sm + (rbase - smb);
        uint32_t ah[2][4], bh[4][2];
        #pragma unroll
        for (int mt = 0; mt < 2; ++mt) {
            const float* xp = (const float*)(sbase + fo[mt]);
            const float r0 = xp[0];
            const float r1 = xp[8];
            const float r2 = xp[4 * XS_STRIDE];
            const float r3 = xp[4 * XS_STRIDE + 8];
            ssr[mt][0] = fmaf(r0, r0, fmaf(r2, r2, ssr[mt][0]));
            ssr[mt][1] = fmaf(r1, r1, fmaf(r3, r3, ssr[mt][1]));
            ah[mt][0] = __float_as_uint(tf32_rna(r0));
            ah[mt][1] = __float_as_uint(tf32_rna(r1));
            ah[mt][2] = __float_as_uint(tf32_rna(r2));
            ah[mt][3] = __float_as_uint(tf32_rna(r3));
        }
        #pragma unroll
        for (int nt = 0; nt < 4; ++nt) {
            const float* bp = (const float*)(sbase + bo[nt]);
            bh[nt][0] = __float_as_uint(bp[0]);
            bh[nt][1] = __float_as_uint(bp[4]);
        }
        #pragma unroll
        for (int mt = 0; mt < 2; ++mt)
            #pragma unroll
            for (int nt = 0; nt < 4; ++nt)
                mma_tf32(d[mt][nt], ah[mt], bh[nt]);

        rbase += STG_BYTES;
        if (rbase == smb + RING_BYTES) rbase = smb;
    }

    // drain outstanding cp.async (targets overlap epilogue region), then reuse ring
    CP_WAIT0();
    __syncthreads();

    // ---- epilogue (ring smem reused) ----
    float* ssim = (float*)sm;                 // [32][132]
    float* sss  = (float*)(sm + SSS_OFF);     // [128]
    #pragma unroll
    for (int mt = 0; mt < 2; ++mt) {
        const int r0 = wpx + mt * 16 + (lane >> 2);
        #pragma unroll
        for (int nt = 0; nt < 4; ++nt) {
            const int n0 = nt * 8 + (lane & 3) * 2;
            ssim[n0 * SSIM_STRIDE + r0]           = d[mt][nt][0];
            ssim[(n0 + 1) * SSIM_STRIDE + r0]     = d[mt][nt][1];
            ssim[n0 * SSIM_STRIDE + r0 + 8]       = d[mt][nt][2];
            ssim[(n0 + 1) * SSIM_STRIDE + r0 + 8] = d[mt][nt][3];
        }
    }
    #pragma unroll
    for (int mt = 0; mt < 2; ++mt)
        #pragma unroll
        for (int j = 0; j < 2; ++j) {
            float vv = ssr[mt][j];
            vv += __shfl_xor_sync(0xffffffffu, vv, 1);
            vv += __shfl_xor_sync(0xffffffffu, vv, 2);
            if ((lane & 3) == 0)
                sss[wpx + mt * 16 + j * 8 + (lane >> 2)] = vv;
        }
    __syncthreads();

    const float inv = 1.0f / fmaxf(sqrtf(sss[tid]), 1e-12f);
    float sims[NCL], m = -1e30f;
    #pragma unroll
    for (int n = 0; n < NCL; ++n) {
        sims[n] = ssim[n * SSIM_STRIDE + tid] * inv;
        m = fmaxf(m, sims[n]);
    }
    float se = 0.0f, ses = 0.0f;
    #pragma unroll
    for (int n = 0; n < NCL; ++n) {
        const float e = __expf(2.0f * (sims[n] - m));
        se += e; ses += e * sims[n];
        sims[n] = e;
    }
    const float r = 1.0f / se;

    if (probs != nullptr && valid) {
        float* op = probs + (size_t)b * NCL * HW + pix;
        #pragma unroll
        for (int n = 0; n < NCL; ++n) op[(size_t)n * HW] = sims[n] * r;
    }

    // ---- loss reduction ----
    float c = valid ? (ses * r) : 0.0f;
    #pragma unroll
    for (int o = 16; o > 0; o >>= 1) c += __shfl_xor_sync(0xffffffffu, c, o);
    if (lane == 0) sred[warp] = c;
    __syncthreads();
    if (tid == 0)
        atomicAdd(&g_accum, (double)(sred[0] + sred[1] + sred[2] + sred[3]));

    // ---- fused finalize: last CTA writes the loss ----
    if (tid == 0 && loss != nullptr) {
        __threadfence();
        const int t = atomicAdd(&g_done, 1);
        if (t == NTILES - 1)
            *loss = (float)(-g_accum / (double)TOTPX);
    }
}

extern "C" void kernel_launch(void* const* d_in, const int* in_sizes, int n_in,
                              void* d_out, int out_size) {
    const float* x        = (const float*)d_in[0];
    const float* clusters = (const float*)d_in[1];
    float* out = (float*)d_out;

    float* probs_ptr = nullptr;
    float* loss_ptr  = nullptr;
    if (out_size >= PROBS_ELEMS) {
        probs_ptr = out + (out_size - PROBS_ELEMS);
        if (out_size > PROBS_ELEMS) loss_ptr = out;
    } else {
        loss_ptr = out;
    }

    normalize_clusters<<<NCL + 1, 256>>>(clusters);
    cluster_main<<<NTILES, TPB>>>(x, probs_ptr, loss_ptr);
}